// round 15
// baseline (speedup 1.0000x reference)
#include <cuda_runtime.h>
#include <math_constants.h>
#include <cstdint>

// ChamferDistanceLoss, B=8, N=4096, D=3 — fused both directions.
// d(i,j) = rn_i + cn_j - 2 p1_i.p2_j computed ONCE per pair.
// R13 structure (block = batch x 256-row x 512-col, XOR col rotation) with the
// inner math packed into fma.rn.f32x2 / add.rn.f32x2: row pairs packed into
// 64-bit regs, candidates staged DUPLICATED (two conflict-free float4 arrays)
// so packed operands come straight off LDS.128.

#define NPTS 4096
#define BATCH 8
#define RPB 256
#define CPB 512
#define RT 16
#define CT 8
#define MAIN_BLOCKS (BATCH * RT * CT)       // 1024
#define THREADS 128
#define NWARPS 4
#define WCOLS (CPB / NWARPS)                // 128
#define RED_BLOCKS 320                      // 256 row-side + 64 col-side
#define RED_THREADS 128

__device__ float g_rowpart[MAIN_BLOCKS * RPB];   // 1 MB
__device__ float g_colpart[MAIN_BLOCKS * CPB];   // 2 MB
__device__ float g_sum[RED_BLOCKS];
__device__ unsigned int g_ticket;                // zero-init; reset each call

typedef unsigned long long u64;
__device__ __forceinline__ u64 pack2(float lo, float hi) {
    u64 v; asm("mov.b64 %0, {%1, %2};" : "=l"(v) : "f"(lo), "f"(hi)); return v;
}
__device__ __forceinline__ void unpack2(u64 v, float& lo, float& hi) {
    asm("mov.b64 {%0, %1}, %2;" : "=f"(lo), "=f"(hi) : "l"(v));
}
__device__ __forceinline__ u64 ffma2(u64 a, u64 b, u64 c) {
    u64 d; asm("fma.rn.f32x2 %0, %1, %2, %3;" : "=l"(d) : "l"(a), "l"(b), "l"(c));
    return d;
}
__device__ __forceinline__ u64 add2(u64 a, u64 b) {
    u64 d; asm("add.rn.f32x2 %0, %1, %2;" : "=l"(d) : "l"(a), "l"(b));
    return d;
}

// ---------------------------------------------------------------------------
__global__ void __launch_bounds__(THREADS, 6)
chamfer_main(const float* __restrict__ p1, const float* __restrict__ p2) {
    __shared__ float4 scA[CPB];                   // {-2x,-2x,-2y,-2y}  8 KB
    __shared__ float4 scB[CPB];                   // {-2z,-2z,cn,cn}    8 KB
    __shared__ float  s_row[NWARPS * RPB];        // 4 KB

    int bx = blockIdx.x;
    int b  = bx >> 7;                             // batch
    int rt = (bx >> 3) & 15;                      // row tile (256 rows)
    int ct = bx & 7;                              // col tile (512 cols)
    const float* __restrict__ rows = p1 + (b * NPTS + rt * RPB) * 3;
    const float* __restrict__ cols = p2 + (b * NPTS + ct * CPB) * 3;

    int t = threadIdx.x, w = t >> 5, lane = t & 31;

    // Stage 512 candidates duplicated: 4 per thread via 3x LDG.128.
    {
        const float4* s4 = (const float4*)cols + 3 * t;
        float4 v0 = s4[0], v1 = s4[1], v2 = s4[2];
        float cx[4] = { v0.x, v0.w, v1.z, v2.y };
        float cy[4] = { v0.y, v1.x, v1.w, v2.z };
        float cz[4] = { v0.z, v1.y, v2.x, v2.w };
        #pragma unroll
        for (int k = 0; k < 4; ++k) {
            float x = cx[k], y = cy[k], z = cz[k];
            float n = fmaf(x, x, fmaf(y, y, z * z));
            scA[4 * t + k] = make_float4(-2.0f * x, -2.0f * x, -2.0f * y, -2.0f * y);
            scB[4 * t + k] = make_float4(-2.0f * z, -2.0f * z, n, n);
        }
    }

    // 8 rows per lane, packed pairwise into f32x2 operands.
    float rnv[8], rm[8];
    u64 rx01, rx23, rx45, rx67, ry01, ry23, ry45, ry67;
    u64 rz01, rz23, rz45, rz67, rn01, rn23, rn45, rn67;
    {
        float rxv[8], ryv[8], rzv[8];
        #pragma unroll
        for (int k = 0; k < 8; ++k) {
            int r = k * 32 + lane;
            rxv[k] = rows[3 * r + 0];
            ryv[k] = rows[3 * r + 1];
            rzv[k] = rows[3 * r + 2];
            rnv[k] = fmaf(rxv[k], rxv[k], fmaf(ryv[k], ryv[k], rzv[k] * rzv[k]));
            rm[k] = CUDART_INF_F;
        }
        rx01 = pack2(rxv[0], rxv[1]); rx23 = pack2(rxv[2], rxv[3]);
        rx45 = pack2(rxv[4], rxv[5]); rx67 = pack2(rxv[6], rxv[7]);
        ry01 = pack2(ryv[0], ryv[1]); ry23 = pack2(ryv[2], ryv[3]);
        ry45 = pack2(ryv[4], ryv[5]); ry67 = pack2(ryv[6], ryv[7]);
        rz01 = pack2(rzv[0], rzv[1]); rz23 = pack2(rzv[2], rzv[3]);
        rz45 = pack2(rzv[4], rzv[5]); rz67 = pack2(rzv[6], rzv[7]);
        rn01 = pack2(rnv[0], rnv[1]); rn23 = pack2(rnv[2], rnv[3]);
        rn45 = pack2(rnv[4], rnv[5]); rn67 = pack2(rnv[6], rnv[7]);
    }
    __syncthreads();

    const char* sbaseA = (const char*)scA;
    const char* sbaseB = (const char*)scB;
    #pragma unroll
    for (int cc = 0; cc < WCOLS / 32; ++cc) {     // 4 groups of 32 cols
        uint32_t off0 = (uint32_t)(w * WCOLS + cc * 32 + lane) * 16u;
        float cm = CUDART_INF_F;
        #pragma unroll 8
        for (int s = 0; s < 32; ++s) {
            uint32_t off = off0 ^ ((uint32_t)s << 4);
            ulonglong2 a = *(const ulonglong2*)(sbaseA + off);  // {-2x.2},{-2y.2}
            ulonglong2 g = *(const ulonglong2*)(sbaseB + off);  // {-2z.2},{cn.2}
            u64 e01 = ffma2(a.x, rx01, ffma2(a.y, ry01, ffma2(g.x, rz01, g.y)));
            u64 e23 = ffma2(a.x, rx23, ffma2(a.y, ry23, ffma2(g.x, rz23, g.y)));
            u64 e45 = ffma2(a.x, rx45, ffma2(a.y, ry45, ffma2(g.x, rz45, g.y)));
            u64 e67 = ffma2(a.x, rx67, ffma2(a.y, ry67, ffma2(g.x, rz67, g.y)));
            float e0, e1, e2, e3, e4, e5, e6, e7;
            unpack2(e01, e0, e1); unpack2(e23, e2, e3);
            unpack2(e45, e4, e5); unpack2(e67, e6, e7);
            rm[0] = fminf(rm[0], e0); rm[1] = fminf(rm[1], e1);
            rm[2] = fminf(rm[2], e2); rm[3] = fminf(rm[3], e3);
            rm[4] = fminf(rm[4], e4); rm[5] = fminf(rm[5], e5);
            rm[6] = fminf(rm[6], e6); rm[7] = fminf(rm[7], e7);
            // col side: full d = e + rn, packed adds (fma pipe, 4 instr)
            u64 d01 = add2(e01, rn01), d23 = add2(e23, rn23);
            u64 d45 = add2(e45, rn45), d67 = add2(e67, rn67);
            float d0, d1, d2, d3, d4, d5, d6, d7;
            unpack2(d01, d0, d1); unpack2(d23, d2, d3);
            unpack2(d45, d4, d5); unpack2(d67, d6, d7);
            float cv = fminf(fminf(fminf(d0, d1), fminf(d2, d3)),
                             fminf(fminf(d4, d5), fminf(d6, d7)));
            cm = fminf(cm, __shfl_xor_sync(0xffffffffu, cv, s));
        }
        g_colpart[bx * CPB + w * WCOLS + cc * 32 + lane] = cm;
    }

    // Row side: fold rn, combine across the 4 warps (same rows) in smem.
    #pragma unroll
    for (int k = 0; k < 8; ++k)
        s_row[w * RPB + k * 32 + lane] = rnv[k] + rm[k];
    __syncthreads();
    #pragma unroll
    for (int rr = t; rr < RPB; rr += THREADS) {
        float v = fminf(fminf(s_row[rr], s_row[RPB + rr]),
                        fminf(s_row[2 * RPB + rr], s_row[3 * RPB + rr]));
        g_rowpart[bx * RPB + rr] = v;
    }
}

// ---------------------------------------------------------------------------
// Reduce (one launch, ticket-merged final) — unchanged from R13.
// ---------------------------------------------------------------------------
__global__ void __launch_bounds__(RED_THREADS)
chamfer_reduce(float* __restrict__ out) {
    __shared__ float wsum[RED_THREADS / 32];
    __shared__ bool s_last;
    int bid = blockIdx.x, t = threadIdx.x;

    float s;
    if (bid < 256) {
        int i = bid * RED_THREADS + t;            // 0..32767 row index
        int b = i >> 12;
        int r = i & (NPTS - 1);
        int rt = r >> 8, rr = r & (RPB - 1);
        float rmin = CUDART_INF_F;
        #pragma unroll
        for (int c = 0; c < CT; ++c)
            rmin = fminf(rmin,
                g_rowpart[((b * RT + rt) * CT + c) * RPB + rr]);
        s = rmin;
    } else {
        int q = (bid - 256) * RED_THREADS + t;    // 0..8191 col-quad index
        int b = q >> 10;
        int g4 = q & 1023;
        int ct = g4 >> 7;
        int cc4 = (g4 & 127) * 4;
        float4 acc = make_float4(CUDART_INF_F, CUDART_INF_F,
                                 CUDART_INF_F, CUDART_INF_F);
        #pragma unroll
        for (int rt = 0; rt < RT; ++rt) {
            const float4 v = *(const float4*)
                &g_colpart[((b * RT + rt) * CT + ct) * CPB + cc4];
            acc.x = fminf(acc.x, v.x);
            acc.y = fminf(acc.y, v.y);
            acc.z = fminf(acc.z, v.z);
            acc.w = fminf(acc.w, v.w);
        }
        s = (acc.x + acc.y) + (acc.z + acc.w);
    }

    #pragma unroll
    for (int off = 16; off > 0; off >>= 1)
        s += __shfl_down_sync(0xffffffffu, s, off);
    if ((t & 31) == 0) wsum[t >> 5] = s;
    __syncthreads();
    if (t == 0) {
        float p = 0.0f;
        #pragma unroll
        for (int ww = 0; ww < RED_THREADS / 32; ++ww) p += wsum[ww];
        g_sum[bid] = p;
        __threadfence();
        unsigned int v = atomicAdd(&g_ticket, 1u);
        s_last = (v == RED_BLOCKS - 1);
    }
    __syncthreads();

    if (s_last) {
        __threadfence();
        float fs = g_sum[t] + g_sum[t + 128] + ((t < 64) ? g_sum[t + 256] : 0.0f);
        #pragma unroll
        for (int off = 16; off > 0; off >>= 1)
            fs += __shfl_down_sync(0xffffffffu, fs, off);
        if ((t & 31) == 0) wsum[t >> 5] = fs;
        __syncthreads();
        if (t == 0) {
            float tot = 0.0f;
            #pragma unroll
            for (int ww = 0; ww < RED_THREADS / 32; ++ww) tot += wsum[ww];
            out[0] = tot * (1.0f / (float)(BATCH * NPTS));
            g_ticket = 0;   // reset for next graph replay
        }
    }
}

extern "C" void kernel_launch(void* const* d_in, const int* in_sizes, int n_in,
                              void* d_out, int out_size) {
    const float* p1 = (const float*)d_in[0];
    const float* p2 = (const float*)d_in[1];
    float* out = (float*)d_out;

    chamfer_main<<<MAIN_BLOCKS, THREADS>>>(p1, p2);
    chamfer_reduce<<<RED_BLOCKS, RED_THREADS>>>(out);
}